// round 13
// baseline (speedup 1.0000x reference)
#include <cuda_runtime.h>
#include <cuda_fp16.h>
#include <cstdint>

// Problem constants: x (32, 64, 64, 64) fp32, codebook (1024, 64) fp32
#define DD     64
#define KK     1024
#define BB     32
#define HWN    4096
#define NPTS   (BB * HWN)

#define MT     128          // points per CTA
#define NC     64           // codes per chunk
#define NCHUNK (KK / NC)    // 16
#define NTHR   128          // 4 warps, two 16-point mtiles per warp
#define MARGIN 2e-3f        // 40x the hi/lo-split score error bound (~5e-5)

typedef unsigned long long ull;

// Codebook B fragments: hi/lo interleaved in ONE uint4 {bh0, bh1, bl0, bl1}.
__device__ uint4 g_b[(KK / 8) * 4 * 32];
__device__ float g_norm[KK];    // EXACT: float4 / 4-acc / (s0+s1)+(s2+s3)
__device__ float g_mh[KK];      // -0.5 * g_norm (approximate filter only)

__device__ __forceinline__ void split16(float v, uint16_t &h, uint16_t &l) {
    __half hh = __float2half_rn(v);
    __half ll = __float2half_rn(v - __half2float(hh));
    h = __half_as_ushort(hh);
    l = __half_as_ushort(ll);
}
__device__ __forceinline__ uint32_t pk(uint16_t a, uint16_t b) {
    return (uint32_t)a | ((uint32_t)b << 16);
}

__device__ __forceinline__ void mma16816(float acc[4], uint4 a, uint32_t b0, uint32_t b1) {
    asm volatile(
        "mma.sync.aligned.m16n8k16.row.col.f32.f16.f16.f32 "
        "{%0,%1,%2,%3},{%4,%5,%6,%7},{%8,%9},{%0,%1,%2,%3};"
        : "+f"(acc[0]), "+f"(acc[1]), "+f"(acc[2]), "+f"(acc[3])
        : "r"(a.x), "r"(a.y), "r"(a.z), "r"(a.w), "r"(b0), "r"(b1));
}

// ---- prep: pack codebook fragments (hi/lo interleaved) + exact ||c||^2 ----
__global__ void cbprep_kernel(const float* __restrict__ cb) {
    int t = blockIdx.x * blockDim.x + threadIdx.x;   // 0..16383
    int lane = t & 31, ks = (t >> 5) & 3, nt = t >> 7;
    int g = lane >> 2, tg = lane & 3;
    int n = nt * 8 + g;
    int k0 = ks * 16 + 2 * tg;
    const float* row = cb + (size_t)n * DD;
    float v0 = row[k0], v1 = row[k0 + 1], v2 = row[k0 + 8], v3 = row[k0 + 9];
    uint16_t h0, l0, h1, l1, h2, l2, h3, l3;
    split16(v0, h0, l0); split16(v1, h1, l1);
    split16(v2, h2, l2); split16(v3, h3, l3);
    g_b[t] = make_uint4(pk(h0, h1), pk(h2, h3), pk(l0, l1), pk(l2, l3));

    if (t < KK) {
        const float4* r4 = (const float4*)(cb + (size_t)t * DD);
        float s0 = 0.f, s1 = 0.f, s2 = 0.f, s3 = 0.f;
        #pragma unroll
        for (int q = 0; q < DD / 4; q++) {
            float4 c = r4[q];
            s0 = fmaf(c.x, c.x, s0);
            s1 = fmaf(c.y, c.y, s1);
            s2 = fmaf(c.z, c.z, s2);
            s3 = fmaf(c.w, c.w, s3);
        }
        float norm = (s0 + s1) + (s2 + s3);
        g_norm[t] = norm;
        g_mh[t]   = -0.5f * norm;
    }
}

// ---- shared layout ----
#define OFF_AH   0            // 1024 x uint4  16 KB; reused as rescue scratch
#define OFF_AL   16384        // 16 KB
#define OFF_MH   32768        // float[1024]    4 KB
#define OFF_SIDX 36864        // int[128]
#define OFF_FLG  37376        // int[128]
#define OFF_NFLG 37888        // int
#define SMEM_TOTAL 38016

// Branch-free top-2 update.
// Strict > keeps the FIRST (lowest-k) max; duplicate max -> sec==best -> flagged.
#define UPD(s, kk, ii)                                   \
    {                                                    \
        float _mn = fminf((s), best[ii]);                \
        bidx[ii] = ((s) > best[ii]) ? (kk) : bidx[ii];   \
        best[ii] = fmaxf((s), best[ii]);                 \
        sec[ii]  = fmaxf(sec[ii], _mn);                  \
    }

__global__ void __launch_bounds__(NTHR, 5) vq_kernel(
    const float* __restrict__ x,
    const float* __restrict__ cb,
    float* __restrict__ out,
    int write_idx
) {
    extern __shared__ char smem[];
    uint4* sah = (uint4*)(smem + OFF_AH);
    uint4* sal = (uint4*)(smem + OFF_AL);
    float* smh = (float*)(smem + OFF_MH);
    int*   sidx = (int*)(smem + OFF_SIDX);
    int*   sflg = (int*)(smem + OFF_FLG);
    int*   nflg = (int*)(smem + OFF_NFLG);

    const int tid = threadIdx.x;
    const int w = tid >> 5, lane = tid & 31;
    const int g = lane >> 2, tg = lane & 3;

    const int p0 = blockIdx.x * MT;
    const int b  = p0 >> 12;
    const int n0 = p0 & (HWN - 1);
    const float* xb = x + (size_t)b * DD * HWN + n0;

    if (tid == 0) *nflg = 0;
    for (int i = tid; i < KK; i += NTHR) smh[i] = g_mh[i];

    // ---- stage A: x[b, k, n0+m] -> fp16 hi/lo fragment layout (one-time) ----
    #pragma unroll
    for (int i = 0; i < 8; i++) {
        int f  = tid + i * NTHR;
        int fl = f & 31, ks = (f >> 5) & 3, mt = f >> 7;
        int fg = fl >> 2, ftg = fl & 3;
        int m  = mt * 16 + fg;
        int k0 = ks * 16 + 2 * ftg;
        const float* p = xb + m;
        const float* q = p + 8;
        float v00 = p[(size_t)k0 * HWN],       v01 = p[(size_t)(k0 + 1) * HWN];
        float v02 = p[(size_t)(k0 + 8) * HWN], v03 = p[(size_t)(k0 + 9) * HWN];
        float v10 = q[(size_t)k0 * HWN],       v11 = q[(size_t)(k0 + 1) * HWN];
        float v12 = q[(size_t)(k0 + 8) * HWN], v13 = q[(size_t)(k0 + 9) * HWN];
        uint16_t h[8], l[8];
        split16(v00, h[0], l[0]); split16(v01, h[1], l[1]);
        split16(v02, h[2], l[2]); split16(v03, h[3], l[3]);
        split16(v10, h[4], l[4]); split16(v11, h[5], l[5]);
        split16(v12, h[6], l[6]); split16(v13, h[7], l[7]);
        uint4 H = make_uint4(pk(h[0], h[1]), pk(h[4], h[5]), pk(h[2], h[3]), pk(h[6], h[7]));
        uint4 L = make_uint4(pk(l[0], l[1]), pk(l[4], l[5]), pk(l[2], l[3]), pk(l[6], l[7]));
        int idx = (mt * 4 + ks) * 32 + fl;
        sah[idx] = H;
        sal[idx] = L;
    }
    __syncthreads();

    float best[4], sec[4];
    int   bidx[4];
    #pragma unroll
    for (int i = 0; i < 4; i++) { best[i] = -3.4e38f; sec[i] = -3.4e38f; bidx[i] = 0; }

    const int mt0 = w * 2, mt1 = w * 2 + 1;

    for (int ch = 0; ch < NCHUNK; ch++) {
        const uint4* bp = g_b + (size_t)ch * 1024 + lane;

        // acc init = -0.5||c||^2 (mh folded in; MMA accumulates dot on top)
        float acc[2][8][4];
        #pragma unroll
        for (int j = 0; j < 8; j++) {
            float2 mhv = *(const float2*)&smh[ch * NC + j * 8 + 2 * tg];
            acc[0][j][0] = mhv.x; acc[0][j][1] = mhv.y;
            acc[0][j][2] = mhv.x; acc[0][j][3] = mhv.y;
            acc[1][j][0] = mhv.x; acc[1][j][1] = mhv.y;
            acc[1][j][2] = mhv.x; acc[1][j][3] = mhv.y;
        }

        #pragma unroll
        for (int ks = 0; ks < 4; ks++) {
            uint4 ah0 = sah[(mt0 * 4 + ks) * 32 + lane];
            uint4 al0 = sal[(mt0 * 4 + ks) * 32 + lane];
            uint4 ah1 = sah[(mt1 * 4 + ks) * 32 + lane];
            uint4 al1 = sal[(mt1 * 4 + ks) * 32 + lane];
            #pragma unroll
            for (int j = 0; j < 8; j++) {
                uint4 bv = __ldg(bp + (j * 4 + ks) * 32);   // {bh0,bh1,bl0,bl1}
                mma16816(acc[0][j], ah0, bv.x, bv.y);
                mma16816(acc[0][j], ah0, bv.z, bv.w);
                mma16816(acc[0][j], al0, bv.x, bv.y);
                mma16816(acc[1][j], ah1, bv.x, bv.y);
                mma16816(acc[1][j], ah1, bv.z, bv.w);
                mma16816(acc[1][j], al1, bv.x, bv.y);
            }
        }

        // branch-free top-2 epilogue (ascending k); scores already include mh
        #pragma unroll
        for (int j = 0; j < 8; j++) {
            int kb = ch * NC + j * 8 + 2 * tg;
            #pragma unroll
            for (int mt = 0; mt < 2; mt++) {
                int ia = mt * 2, ib2 = mt * 2 + 1;
                UPD(acc[mt][j][0], kb,     ia);
                UPD(acc[mt][j][1], kb + 1, ia);
                UPD(acc[mt][j][2], kb,     ib2);
                UPD(acc[mt][j][3], kb + 1, ib2);
            }
        }
    }

    // cross-lane top-2 merge (4 lanes per point), index tie-break
    #pragma unroll
    for (int i = 0; i < 4; i++) {
        #pragma unroll
        for (int m = 1; m <= 2; m <<= 1) {
            float ob = __shfl_xor_sync(0xffffffffu, best[i], m);
            float os = __shfl_xor_sync(0xffffffffu, sec[i], m);
            int   oi = __shfl_xor_sync(0xffffffffu, bidx[i], m);
            if (ob > best[i] || (ob == best[i] && oi < bidx[i])) {
                float t = best[i];
                best[i] = ob; bidx[i] = oi;
                sec[i] = (os > t) ? os : t;
            } else {
                sec[i] = (ob > sec[i]) ? ob : sec[i];
            }
        }
    }
    if (tg == 0) {
        #pragma unroll
        for (int i = 0; i < 4; i++) {
            int pl = w * 32 + (i >> 1) * 16 + (i & 1) * 8 + g;
            sidx[pl] = bidx[i];
            if (best[i] - sec[i] < MARGIN) {
                int slot = atomicAdd(nflg, 1);
                if (slot < MT) sflg[slot] = pl;
            }
        }
    }
    __syncthreads();

    // ---- exact fp32 rescue (verified: bit-matches the reference):
    //      dot: float4 / 4-acc / (d0+d1)+(d2+d3); score = fmaf(-2, dot, g_norm[k]);
    //      strict < argmin ascending k; cross-lane index tie-break. ----
    {
        int nfr = *nflg;
        int overflow = (nfr > MT);
        int nf = overflow ? MT : nfr;
        float* xs = (float*)(smem + OFF_AH) + w * 64;   // sah dead now
        for (int f = w; f < nf; f += 4) {
            int pl = overflow ? f : sflg[f];
            xs[lane]      = xb[(size_t)lane * HWN + pl];
            xs[lane + 32] = xb[(size_t)(lane + 32) * HWN + pl];
            __syncwarp();
            float bb = 3.4e38f;
            int   bi = 0;
            for (int j = 0; j < 32; j++) {
                int k = j * 32 + lane;
                const float4* crow = (const float4*)(cb + (size_t)k * DD);
                float d0 = 0.f, d1 = 0.f, d2 = 0.f, d3 = 0.f;
                #pragma unroll
                for (int q = 0; q < 16; q++) {
                    float4 c = __ldg(crow + q);
                    d0 = fmaf(xs[4 * q + 0], c.x, d0);
                    d1 = fmaf(xs[4 * q + 1], c.y, d1);
                    d2 = fmaf(xs[4 * q + 2], c.z, d2);
                    d3 = fmaf(xs[4 * q + 3], c.w, d3);
                }
                float dot = (d0 + d1) + (d2 + d3);
                float s   = fmaf(-2.0f, dot, __ldg(&g_norm[k]));
                if (s < bb) { bb = s; bi = k; }
            }
            #pragma unroll
            for (int m = 16; m >= 1; m >>= 1) {
                float ob = __shfl_xor_sync(0xffffffffu, bb, m);
                int   oi = __shfl_xor_sync(0xffffffffu, bi, m);
                if (ob < bb || (ob == bb && oi < bi)) { bb = ob; bi = oi; }
            }
            if (lane == 0) sidx[pl] = bi;
            __syncwarp();
        }
    }
    __syncthreads();

    // exact fp32 gather, coalesced over points
    float* ob = out + (size_t)b * DD * HWN + n0;
    #pragma unroll
    for (int i = tid; i < MT * DD; i += NTHR) {
        int pl = i & (MT - 1);
        int d  = i >> 7;
        ob[(size_t)d * HWN + pl] = __ldg(&cb[(size_t)sidx[pl] * DD + d]);
    }
    if (write_idx)
        out[(size_t)BB * DD * HWN + p0 + tid] = (float)sidx[tid];
}

extern "C" void kernel_launch(void* const* d_in, const int* in_sizes, int n_in,
                              void* d_out, int out_size) {
    const float* x  = (const float*)d_in[0];
    const float* cb = (const float*)d_in[1];
    float* out = (float*)d_out;

    static int inited = 0;
    if (!inited) {
        cudaFuncSetAttribute(vq_kernel, cudaFuncAttributeMaxDynamicSharedMemorySize, SMEM_TOTAL);
        inited = 1;
    }

    cbprep_kernel<<<64, 256>>>(cb);

    int write_idx = (out_size >= BB * DD * HWN + NPTS) ? 1 : 0;
    vq_kernel<<<NPTS / MT, NTHR, SMEM_TOTAL>>>(x, cb, out, write_idx);
}

// round 14
// speedup vs baseline: 1.1313x; 1.1313x over previous
#include <cuda_runtime.h>
#include <cuda_fp16.h>
#include <cstdint>

// Problem constants: x (32, 64, 64, 64) fp32, codebook (1024, 64) fp32
#define DD     64
#define KK     1024
#define BB     32
#define HWN    4096
#define NPTS   (BB * HWN)

#define MT     128          // points per CTA
#define NC     64           // codes per chunk
#define NCHUNK (KK / NC)    // 16
#define NTHR   256          // 8 warps, ONE 16-point mtile per warp (A fits in regs)
#define MARGIN 2e-3f        // 40x the hi/lo-split score error bound (~5e-5)

typedef unsigned long long ull;

// Codebook B fragments: hi/lo interleaved in ONE uint4 {bh0, bh1, bl0, bl1}.
__device__ uint4 g_b[(KK / 8) * 4 * 32];
__device__ float g_norm[KK];    // EXACT: float4 / 4-acc / (s0+s1)+(s2+s3)
__device__ float g_mh[KK];      // -0.5 * g_norm (approximate filter only)

__device__ __forceinline__ void split16(float v, uint16_t &h, uint16_t &l) {
    __half hh = __float2half_rn(v);
    __half ll = __float2half_rn(v - __half2float(hh));
    h = __half_as_ushort(hh);
    l = __half_as_ushort(ll);
}
__device__ __forceinline__ uint32_t pk(uint16_t a, uint16_t b) {
    return (uint32_t)a | ((uint32_t)b << 16);
}

__device__ __forceinline__ void mma16816(float acc[4], uint4 a, uint32_t b0, uint32_t b1) {
    asm volatile(
        "mma.sync.aligned.m16n8k16.row.col.f32.f16.f16.f32 "
        "{%0,%1,%2,%3},{%4,%5,%6,%7},{%8,%9},{%0,%1,%2,%3};"
        : "+f"(acc[0]), "+f"(acc[1]), "+f"(acc[2]), "+f"(acc[3])
        : "r"(a.x), "r"(a.y), "r"(a.z), "r"(a.w), "r"(b0), "r"(b1));
}

// ---- prep: pack codebook fragments (hi/lo interleaved) + exact ||c||^2 ----
__global__ void cbprep_kernel(const float* __restrict__ cb) {
    int t = blockIdx.x * blockDim.x + threadIdx.x;   // 0..16383
    int lane = t & 31, ks = (t >> 5) & 3, nt = t >> 7;
    int g = lane >> 2, tg = lane & 3;
    int n = nt * 8 + g;
    int k0 = ks * 16 + 2 * tg;
    const float* row = cb + (size_t)n * DD;
    float v0 = row[k0], v1 = row[k0 + 1], v2 = row[k0 + 8], v3 = row[k0 + 9];
    uint16_t h0, l0, h1, l1, h2, l2, h3, l3;
    split16(v0, h0, l0); split16(v1, h1, l1);
    split16(v2, h2, l2); split16(v3, h3, l3);
    g_b[t] = make_uint4(pk(h0, h1), pk(h2, h3), pk(l0, l1), pk(l2, l3));

    if (t < KK) {
        const float4* r4 = (const float4*)(cb + (size_t)t * DD);
        float s0 = 0.f, s1 = 0.f, s2 = 0.f, s3 = 0.f;
        #pragma unroll
        for (int q = 0; q < DD / 4; q++) {
            float4 c = r4[q];
            s0 = fmaf(c.x, c.x, s0);
            s1 = fmaf(c.y, c.y, s1);
            s2 = fmaf(c.z, c.z, s2);
            s3 = fmaf(c.w, c.w, s3);
        }
        float norm = (s0 + s1) + (s2 + s3);
        g_norm[t] = norm;
        g_mh[t]   = -0.5f * norm;
    }
}

// ---- shared layout ----
#define OFF_AH   0            // 1024 x uint4  16 KB; reused as rescue scratch
#define OFF_AL   16384        // 16 KB
#define OFF_MH   32768        // float[1024]    4 KB
#define OFF_SIDX 36864        // int[128]
#define OFF_FLG  37376        // int[128]
#define OFF_NFLG 37888        // int
#define SMEM_TOTAL 38016

// Branch-free top-2 update.
// Strict > keeps the FIRST (lowest-k) max; duplicate max -> sec==best -> flagged.
#define UPD(s, kk, ii)                                   \
    {                                                    \
        float _mn = fminf((s), best[ii]);                \
        bidx[ii] = ((s) > best[ii]) ? (kk) : bidx[ii];   \
        best[ii] = fmaxf((s), best[ii]);                 \
        sec[ii]  = fmaxf(sec[ii], _mn);                  \
    }

__global__ void __launch_bounds__(NTHR, 2) vq_kernel(
    const float* __restrict__ x,
    const float* __restrict__ cb,
    float* __restrict__ out,
    int write_idx
) {
    extern __shared__ char smem[];
    uint4* sah = (uint4*)(smem + OFF_AH);
    uint4* sal = (uint4*)(smem + OFF_AL);
    float* smh = (float*)(smem + OFF_MH);
    int*   sidx = (int*)(smem + OFF_SIDX);
    int*   sflg = (int*)(smem + OFF_FLG);
    int*   nflg = (int*)(smem + OFF_NFLG);

    const int tid = threadIdx.x;
    const int w = tid >> 5, lane = tid & 31;
    const int g = lane >> 2, tg = lane & 3;

    const int p0 = blockIdx.x * MT;
    const int b  = p0 >> 12;
    const int n0 = p0 & (HWN - 1);
    const float* xb = x + (size_t)b * DD * HWN + n0;

    if (tid == 0) *nflg = 0;
    for (int i = tid; i < KK; i += NTHR) smh[i] = g_mh[i];

    // ---- stage A: x[b, k, n0+m] -> fp16 hi/lo fragment layout (one-time) ----
    #pragma unroll
    for (int i = 0; i < 4; i++) {
        int f  = tid + i * NTHR;
        int fl = f & 31, ks = (f >> 5) & 3, mt = f >> 7;   // mt = 0..7 (one per warp)
        int fg = fl >> 2, ftg = fl & 3;
        int m  = mt * 16 + fg;
        int k0 = ks * 16 + 2 * ftg;
        const float* p = xb + m;
        const float* q = p + 8;
        float v00 = p[(size_t)k0 * HWN],       v01 = p[(size_t)(k0 + 1) * HWN];
        float v02 = p[(size_t)(k0 + 8) * HWN], v03 = p[(size_t)(k0 + 9) * HWN];
        float v10 = q[(size_t)k0 * HWN],       v11 = q[(size_t)(k0 + 1) * HWN];
        float v12 = q[(size_t)(k0 + 8) * HWN], v13 = q[(size_t)(k0 + 9) * HWN];
        uint16_t h[8], l[8];
        split16(v00, h[0], l[0]); split16(v01, h[1], l[1]);
        split16(v02, h[2], l[2]); split16(v03, h[3], l[3]);
        split16(v10, h[4], l[4]); split16(v11, h[5], l[5]);
        split16(v12, h[6], l[6]); split16(v13, h[7], l[7]);
        uint4 H = make_uint4(pk(h[0], h[1]), pk(h[4], h[5]), pk(h[2], h[3]), pk(h[6], h[7]));
        uint4 L = make_uint4(pk(l[0], l[1]), pk(l[4], l[5]), pk(l[2], l[3]), pk(l[6], l[7]));
        int idx = (mt * 4 + ks) * 32 + fl;
        sah[idx] = H;
        sal[idx] = L;
    }
    __syncthreads();

    // ---- A fragments -> registers, once for the whole kernel ----
    uint4 AH[4], AL[4];
    #pragma unroll
    for (int ks = 0; ks < 4; ks++) {
        AH[ks] = sah[(w * 4 + ks) * 32 + lane];
        AL[ks] = sal[(w * 4 + ks) * 32 + lane];
    }

    float best[2], sec[2];
    int   bidx[2];
    #pragma unroll
    for (int i = 0; i < 2; i++) { best[i] = -3.4e38f; sec[i] = -3.4e38f; bidx[i] = 0; }

    for (int ch = 0; ch < NCHUNK; ch++) {
        const uint4* bp = g_b + (size_t)ch * 1024 + lane;

        // acc init = -0.5||c||^2 (mh folded in; MMA accumulates dot on top)
        float acc[8][4];
        #pragma unroll
        for (int j = 0; j < 8; j++) {
            float2 mhv = *(const float2*)&smh[ch * NC + j * 8 + 2 * tg];
            acc[j][0] = mhv.x; acc[j][1] = mhv.y;
            acc[j][2] = mhv.x; acc[j][3] = mhv.y;
        }

        #pragma unroll
        for (int ks = 0; ks < 4; ks++) {
            #pragma unroll
            for (int j = 0; j < 8; j++) {
                uint4 bv = __ldg(bp + (j * 4 + ks) * 32);   // {bh0,bh1,bl0,bl1}
                mma16816(acc[j], AH[ks], bv.x, bv.y);
                mma16816(acc[j], AH[ks], bv.z, bv.w);
                mma16816(acc[j], AL[ks], bv.x, bv.y);
            }
        }

        // branch-free top-2 epilogue (ascending k); scores already include mh
        #pragma unroll
        for (int j = 0; j < 8; j++) {
            int kb = ch * NC + j * 8 + 2 * tg;
            UPD(acc[j][0], kb,     0);
            UPD(acc[j][1], kb + 1, 0);
            UPD(acc[j][2], kb,     1);
            UPD(acc[j][3], kb + 1, 1);
        }
    }

    // cross-lane top-2 merge (4 lanes per point), index tie-break
    #pragma unroll
    for (int i = 0; i < 2; i++) {
        #pragma unroll
        for (int m = 1; m <= 2; m <<= 1) {
            float ob = __shfl_xor_sync(0xffffffffu, best[i], m);
            float os = __shfl_xor_sync(0xffffffffu, sec[i], m);
            int   oi = __shfl_xor_sync(0xffffffffu, bidx[i], m);
            if (ob > best[i] || (ob == best[i] && oi < bidx[i])) {
                float t = best[i];
                best[i] = ob; bidx[i] = oi;
                sec[i] = (os > t) ? os : t;
            } else {
                sec[i] = (ob > sec[i]) ? ob : sec[i];
            }
        }
    }
    if (tg == 0) {
        #pragma unroll
        for (int i = 0; i < 2; i++) {
            int pl = w * 16 + i * 8 + g;
            sidx[pl] = bidx[i];
            if (best[i] - sec[i] < MARGIN) {
                int slot = atomicAdd(nflg, 1);
                if (slot < MT) sflg[slot] = pl;
            }
        }
    }
    __syncthreads();

    // ---- exact fp32 rescue (verified: bit-matches the reference):
    //      dot: float4 / 4-acc / (d0+d1)+(d2+d3); score = fmaf(-2, dot, g_norm[k]);
    //      strict < argmin ascending k; cross-lane index tie-break. ----
    {
        int nfr = *nflg;
        int overflow = (nfr > MT);
        int nf = overflow ? MT : nfr;
        float* xs = (float*)(smem + OFF_AH) + w * 64;   // sah dead now
        for (int f = w; f < nf; f += 8) {
            int pl = overflow ? f : sflg[f];
            xs[lane]      = xb[(size_t)lane * HWN + pl];
            xs[lane + 32] = xb[(size_t)(lane + 32) * HWN + pl];
            __syncwarp();
            float bb = 3.4e38f;
            int   bi = 0;
            for (int j = 0; j < 32; j++) {
                int k = j * 32 + lane;
                const float4* crow = (const float4*)(cb + (size_t)k * DD);
                float d0 = 0.f, d1 = 0.f, d2 = 0.f, d3 = 0.f;
                #pragma unroll
                for (int q = 0; q < 16; q++) {
                    float4 c = __ldg(crow + q);
                    d0 = fmaf(xs[4 * q + 0], c.x, d0);
                    d1 = fmaf(xs[4 * q + 1], c.y, d1);
                    d2 = fmaf(xs[4 * q + 2], c.z, d2);
                    d3 = fmaf(xs[4 * q + 3], c.w, d3);
                }
                float dot = (d0 + d1) + (d2 + d3);
                float s   = fmaf(-2.0f, dot, __ldg(&g_norm[k]));
                if (s < bb) { bb = s; bi = k; }
            }
            #pragma unroll
            for (int m = 16; m >= 1; m >>= 1) {
                float ob = __shfl_xor_sync(0xffffffffu, bb, m);
                int   oi = __shfl_xor_sync(0xffffffffu, bi, m);
                if (ob < bb || (ob == bb && oi < bi)) { bb = ob; bi = oi; }
            }
            if (lane == 0) sidx[pl] = bi;
            __syncwarp();
        }
    }
    __syncthreads();

    // exact fp32 gather, coalesced over points
    float* ob = out + (size_t)b * DD * HWN + n0;
    #pragma unroll
    for (int i = tid; i < MT * DD; i += NTHR) {
        int pl = i & (MT - 1);
        int d  = i >> 7;
        ob[(size_t)d * HWN + pl] = __ldg(&cb[(size_t)sidx[pl] * DD + d]);
    }
    if (write_idx && tid < MT)
        out[(size_t)BB * DD * HWN + p0 + tid] = (float)sidx[tid];
}

extern "C" void kernel_launch(void* const* d_in, const int* in_sizes, int n_in,
                              void* d_out, int out_size) {
    const float* x  = (const float*)d_in[0];
    const float* cb = (const float*)d_in[1];
    float* out = (float*)d_out;

    static int inited = 0;
    if (!inited) {
        cudaFuncSetAttribute(vq_kernel, cudaFuncAttributeMaxDynamicSharedMemorySize, SMEM_TOTAL);
        inited = 1;
    }

    cbprep_kernel<<<64, 256>>>(cb);

    int write_idx = (out_size >= BB * DD * HWN + NPTS) ? 1 : 0;
    vq_kernel<<<NPTS / MT, NTHR, SMEM_TOTAL>>>(x, cb, out, write_idx);
}

// round 15
// speedup vs baseline: 1.1569x; 1.0226x over previous
#include <cuda_runtime.h>
#include <cuda_fp16.h>
#include <cstdint>

// Problem constants: x (32, 64, 64, 64) fp32, codebook (1024, 64) fp32
#define DD     64
#define KK     1024
#define BB     32
#define HWN    4096
#define NPTS   (BB * HWN)

#define MT     128          // points per CTA
#define NC     64           // codes per chunk
#define NCHUNK (KK / NC)    // 16
#define NTHR   256          // 8 warps, ONE 16-point mtile per warp (A in regs)
#define MARGIN 2e-3f        // 40x the hi/lo-split score error bound (~5e-5)

typedef unsigned long long ull;

// Codebook B fragments: hi/lo interleaved in ONE uint4 {bh0, bh1, bl0, bl1}.
__device__ uint4 g_b[(KK / 8) * 4 * 32];
__device__ float g_norm[KK];    // EXACT: float4 / 4-acc / (s0+s1)+(s2+s3)
__device__ float g_mh[KK];      // -0.5 * g_norm (approximate filter only)

__device__ __forceinline__ void split16(float v, uint16_t &h, uint16_t &l) {
    __half hh = __float2half_rn(v);
    __half ll = __float2half_rn(v - __half2float(hh));
    h = __half_as_ushort(hh);
    l = __half_as_ushort(ll);
}
__device__ __forceinline__ uint32_t pk(uint16_t a, uint16_t b) {
    return (uint32_t)a | ((uint32_t)b << 16);
}

__device__ __forceinline__ void mma16816(float acc[4], uint4 a, uint32_t b0, uint32_t b1) {
    asm volatile(
        "mma.sync.aligned.m16n8k16.row.col.f32.f16.f16.f32 "
        "{%0,%1,%2,%3},{%4,%5,%6,%7},{%8,%9},{%0,%1,%2,%3};"
        : "+f"(acc[0]), "+f"(acc[1]), "+f"(acc[2]), "+f"(acc[3])
        : "r"(a.x), "r"(a.y), "r"(a.z), "r"(a.w), "r"(b0), "r"(b1));
}

// ---- prep: pack codebook fragments (hi/lo interleaved) + exact ||c||^2 ----
__global__ void cbprep_kernel(const float* __restrict__ cb) {
    int t = blockIdx.x * blockDim.x + threadIdx.x;   // 0..16383
    int lane = t & 31, ks = (t >> 5) & 3, nt = t >> 7;
    int g = lane >> 2, tg = lane & 3;
    int n = nt * 8 + g;
    int k0 = ks * 16 + 2 * tg;
    const float* row = cb + (size_t)n * DD;
    float v0 = row[k0], v1 = row[k0 + 1], v2 = row[k0 + 8], v3 = row[k0 + 9];
    uint16_t h0, l0, h1, l1, h2, l2, h3, l3;
    split16(v0, h0, l0); split16(v1, h1, l1);
    split16(v2, h2, l2); split16(v3, h3, l3);
    g_b[t] = make_uint4(pk(h0, h1), pk(h2, h3), pk(l0, l1), pk(l2, l3));

    if (t < KK) {
        const float4* r4 = (const float4*)(cb + (size_t)t * DD);
        float s0 = 0.f, s1 = 0.f, s2 = 0.f, s3 = 0.f;
        #pragma unroll
        for (int q = 0; q < DD / 4; q++) {
            float4 c = r4[q];
            s0 = fmaf(c.x, c.x, s0);
            s1 = fmaf(c.y, c.y, s1);
            s2 = fmaf(c.z, c.z, s2);
            s3 = fmaf(c.w, c.w, s3);
        }
        float norm = (s0 + s1) + (s2 + s3);
        g_norm[t] = norm;
        g_mh[t]   = -0.5f * norm;
    }
}

// ---- shared layout ----
#define OFF_AH   0            // 1024 x uint4  16 KB; reused as rescue scratch
#define OFF_AL   16384        // 16 KB
#define OFF_MH   32768        // float[1024]    4 KB
#define OFF_SIDX 36864        // int[128]
#define OFF_FLG  37376        // int[128]
#define OFF_NFLG 37888        // int
#define SMEM_TOTAL 38016

// Branch-free top-2 update.
// Strict > keeps the FIRST (lowest-k) max; duplicate max -> sec==best -> flagged.
#define UPD(s, kk, ii)                                   \
    {                                                    \
        float _mn = fminf((s), best[ii]);                \
        bidx[ii] = ((s) > best[ii]) ? (kk) : bidx[ii];   \
        best[ii] = fmaxf((s), best[ii]);                 \
        sec[ii]  = fmaxf(sec[ii], _mn);                  \
    }

__global__ void __launch_bounds__(NTHR, 2) vq_kernel(
    const float* __restrict__ x,
    const float* __restrict__ cb,
    float* __restrict__ out,
    int write_idx
) {
    extern __shared__ char smem[];
    uint4* sah = (uint4*)(smem + OFF_AH);
    uint4* sal = (uint4*)(smem + OFF_AL);
    float* smh = (float*)(smem + OFF_MH);
    int*   sidx = (int*)(smem + OFF_SIDX);
    int*   sflg = (int*)(smem + OFF_FLG);
    int*   nflg = (int*)(smem + OFF_NFLG);

    const int tid = threadIdx.x;
    const int w = tid >> 5, lane = tid & 31;
    const int g = lane >> 2, tg = lane & 3;

    const int p0 = blockIdx.x * MT;
    const int b  = p0 >> 12;
    const int n0 = p0 & (HWN - 1);
    const float* xb = x + (size_t)b * DD * HWN + n0;

    if (tid == 0) *nflg = 0;
    for (int i = tid; i < KK; i += NTHR) smh[i] = g_mh[i];

    // ---- stage A: x[b, k, n0+m] -> fp16 hi/lo fragment layout (one-time) ----
    #pragma unroll
    for (int i = 0; i < 4; i++) {
        int f  = tid + i * NTHR;
        int fl = f & 31, ks = (f >> 5) & 3, mt = f >> 7;   // mt = 0..7 (one per warp)
        int fg = fl >> 2, ftg = fl & 3;
        int m  = mt * 16 + fg;
        int k0 = ks * 16 + 2 * ftg;
        const float* p = xb + m;
        const float* q = p + 8;
        float v00 = p[(size_t)k0 * HWN],       v01 = p[(size_t)(k0 + 1) * HWN];
        float v02 = p[(size_t)(k0 + 8) * HWN], v03 = p[(size_t)(k0 + 9) * HWN];
        float v10 = q[(size_t)k0 * HWN],       v11 = q[(size_t)(k0 + 1) * HWN];
        float v12 = q[(size_t)(k0 + 8) * HWN], v13 = q[(size_t)(k0 + 9) * HWN];
        uint16_t h[8], l[8];
        split16(v00, h[0], l[0]); split16(v01, h[1], l[1]);
        split16(v02, h[2], l[2]); split16(v03, h[3], l[3]);
        split16(v10, h[4], l[4]); split16(v11, h[5], l[5]);
        split16(v12, h[6], l[6]); split16(v13, h[7], l[7]);
        uint4 H = make_uint4(pk(h[0], h[1]), pk(h[4], h[5]), pk(h[2], h[3]), pk(h[6], h[7]));
        uint4 L = make_uint4(pk(l[0], l[1]), pk(l[4], l[5]), pk(l[2], l[3]), pk(l[6], l[7]));
        int idx = (mt * 4 + ks) * 32 + fl;
        sah[idx] = H;
        sal[idx] = L;
    }
    __syncthreads();

    // ---- A fragments -> registers, once for the whole kernel ----
    uint4 AH[4], AL[4];
    #pragma unroll
    for (int ks = 0; ks < 4; ks++) {
        AH[ks] = sah[(w * 4 + ks) * 32 + lane];
        AL[ks] = sal[(w * 4 + ks) * 32 + lane];
    }

    float best[2], sec[2];
    int   bidx[2];
    #pragma unroll
    for (int i = 0; i < 2; i++) { best[i] = -3.4e38f; sec[i] = -3.4e38f; bidx[i] = 0; }

    // ---- double-buffered B pipeline: batch = (ks, j-group of 4) -> 4 LDG + 12 MMA
    //      batch index bt: ks = bt>>1, jgrp = (bt&1)*4; B frag offset (j*4+ks)*32.
    uint4 bvA[4], bvB[4];
    #pragma unroll
    for (int jj = 0; jj < 4; jj++)          // prime: ch=0, bt=0 (ks=0, j=0..3)
        bvA[jj] = __ldg(g_b + lane + (jj * 4) * 32);

    for (int ch = 0; ch < NCHUNK; ch++) {
        // acc init = -0.5||c||^2 (mh folded in; MMA accumulates dot on top)
        float acc[8][4];
        #pragma unroll
        for (int j = 0; j < 8; j++) {
            float2 mhv = *(const float2*)&smh[ch * NC + j * 8 + 2 * tg];
            acc[j][0] = mhv.x; acc[j][1] = mhv.y;
            acc[j][2] = mhv.x; acc[j][3] = mhv.y;
        }

        #pragma unroll
        for (int bt = 0; bt < 8; bt++) {
            uint4* cur = (bt & 1) ? bvB : bvA;
            uint4* nxt = (bt & 1) ? bvA : bvB;
            // prefetch NEXT batch (wraps into next chunk; last wraps to ch 0 harmlessly)
            int nb  = bt + 1;
            int nch = (ch + (nb >> 3)) & (NCHUNK - 1);
            nb &= 7;
            int nks = nb >> 1, njg = (nb & 1) * 4;
            const uint4* np = g_b + (size_t)nch * 1024 + lane;
            #pragma unroll
            for (int jj = 0; jj < 4; jj++)
                nxt[jj] = __ldg(np + ((njg + jj) * 4 + nks) * 32);

            // 12 MMAs, same-acc RAW distance 4
            int ks = bt >> 1, jg = (bt & 1) * 4;
            #pragma unroll
            for (int jj = 0; jj < 4; jj++) mma16816(acc[jg + jj], AH[ks], cur[jj].x, cur[jj].y);
            #pragma unroll
            for (int jj = 0; jj < 4; jj++) mma16816(acc[jg + jj], AH[ks], cur[jj].z, cur[jj].w);
            #pragma unroll
            for (int jj = 0; jj < 4; jj++) mma16816(acc[jg + jj], AL[ks], cur[jj].x, cur[jj].y);
        }

        // branch-free top-2 epilogue (ascending k); scores already include mh
        #pragma unroll
        for (int j = 0; j < 8; j++) {
            int kb = ch * NC + j * 8 + 2 * tg;
            UPD(acc[j][0], kb,     0);
            UPD(acc[j][1], kb + 1, 0);
            UPD(acc[j][2], kb,     1);
            UPD(acc[j][3], kb + 1, 1);
        }
    }

    // cross-lane top-2 merge (4 lanes per point), index tie-break
    #pragma unroll
    for (int i = 0; i < 2; i++) {
        #pragma unroll
        for (int m = 1; m <= 2; m <<= 1) {
            float ob = __shfl_xor_sync(0xffffffffu, best[i], m);
            float os = __shfl_xor_sync(0xffffffffu, sec[i], m);
            int   oi = __shfl_xor_sync(0xffffffffu, bidx[i], m);
            if (ob > best[i] || (ob == best[i] && oi < bidx[i])) {
                float t = best[i];
                best[i] = ob; bidx[i] = oi;
                sec[i] = (os > t) ? os : t;
            } else {
                sec[i] = (ob > sec[i]) ? ob : sec[i];
            }
        }
    }
    if (tg == 0) {
        #pragma unroll
        for (int i = 0; i < 2; i++) {
            int pl = w * 16 + i * 8 + g;
            sidx[pl] = bidx[i];
            if (best[i] - sec[i] < MARGIN) {
                int slot = atomicAdd(nflg, 1);
                if (slot < MT) sflg[slot] = pl;
            }
        }
    }
    __syncthreads();

    // ---- exact fp32 rescue (verified: bit-matches the reference):
    //      dot: float4 / 4-acc / (d0+d1)+(d2+d3); score = fmaf(-2, dot, g_norm[k]);
    //      strict < argmin ascending k; cross-lane index tie-break. ----
    {
        int nfr = *nflg;
        int overflow = (nfr > MT);
        int nf = overflow ? MT : nfr;
        float* xs = (float*)(smem + OFF_AH) + w * 64;   // sah dead now
        for (int f = w; f < nf; f += 8) {
            int pl = overflow ? f : sflg[f];
            xs[lane]      = xb[(size_t)lane * HWN + pl];
            xs[lane + 32] = xb[(size_t)(lane + 32) * HWN + pl];
            __syncwarp();
            float bb = 3.4e38f;
            int   bi = 0;
            for (int j = 0; j < 32; j++) {
                int k = j * 32 + lane;
                const float4* crow = (const float4*)(cb + (size_t)k * DD);
                float d0 = 0.f, d1 = 0.f, d2 = 0.f, d3 = 0.f;
                #pragma unroll
                for (int q = 0; q < 16; q++) {
                    float4 c = __ldg(crow + q);
                    d0 = fmaf(xs[4 * q + 0], c.x, d0);
                    d1 = fmaf(xs[4 * q + 1], c.y, d1);
                    d2 = fmaf(xs[4 * q + 2], c.z, d2);
                    d3 = fmaf(xs[4 * q + 3], c.w, d3);
                }
                float dot = (d0 + d1) + (d2 + d3);
                float s   = fmaf(-2.0f, dot, __ldg(&g_norm[k]));
                if (s < bb) { bb = s; bi = k; }
            }
            #pragma unroll
            for (int m = 16; m >= 1; m >>= 1) {
                float ob = __shfl_xor_sync(0xffffffffu, bb, m);
                int   oi = __shfl_xor_sync(0xffffffffu, bi, m);
                if (ob < bb || (ob == bb && oi < bi)) { bb = ob; bi = oi; }
            }
            if (lane == 0) sidx[pl] = bi;
            __syncwarp();
        }
    }
    __syncthreads();

    // exact fp32 gather, coalesced over points
    float* ob = out + (size_t)b * DD * HWN + n0;
    #pragma unroll
    for (int i = tid; i < MT * DD; i += NTHR) {
        int pl = i & (MT - 1);
        int d  = i >> 7;
        ob[(size_t)d * HWN + pl] = __ldg(&cb[(size_t)sidx[pl] * DD + d]);
    }
    if (write_idx && tid < MT)
        out[(size_t)BB * DD * HWN + p0 + tid] = (float)sidx[tid];
}

extern "C" void kernel_launch(void* const* d_in, const int* in_sizes, int n_in,
                              void* d_out, int out_size) {
    const float* x  = (const float*)d_in[0];
    const float* cb = (const float*)d_in[1];
    float* out = (float*)d_out;

    static int inited = 0;
    if (!inited) {
        cudaFuncSetAttribute(vq_kernel, cudaFuncAttributeMaxDynamicSharedMemorySize, SMEM_TOTAL);
        inited = 1;
    }

    cbprep_kernel<<<64, 256>>>(cb);

    int write_idx = (out_size >= BB * DD * HWN + NPTS) ? 1 : 0;
    vq_kernel<<<NPTS / MT, NTHR, SMEM_TOTAL>>>(x, cb, out, write_idx);
}

// round 16
// speedup vs baseline: 1.3172x; 1.1386x over previous
#include <cuda_runtime.h>
#include <cuda_fp16.h>
#include <cstdint>

// Problem constants: x (32, 64, 64, 64) fp32, codebook (1024, 64) fp32
#define DD     64
#define KK     1024
#define BB     32
#define HWN    4096
#define NPTS   (BB * HWN)

#define MT     128          // points per CTA
#define NC     64           // codes per chunk
#define NCHUNK (KK / NC)    // 16
#define NTHR   256          // 8 warps, ONE 16-point mtile per warp (A in regs)
#define MARGIN 2e-3f        // 40x the hi/lo-split score error bound (~5e-5)

typedef unsigned long long ull;

// Codebook B fragments: hi/lo interleaved in ONE uint4 {bh0, bh1, bl0, bl1}.
__device__ uint4 g_b[(KK / 8) * 4 * 32];
__device__ float g_norm[KK];    // EXACT: float4 / 4-acc / (s0+s1)+(s2+s3)
__device__ float g_mh[KK];      // -0.5 * g_norm (approximate filter only)

__device__ __forceinline__ void split16(float v, uint16_t &h, uint16_t &l) {
    __half hh = __float2half_rn(v);
    __half ll = __float2half_rn(v - __half2float(hh));
    h = __half_as_ushort(hh);
    l = __half_as_ushort(ll);
}
__device__ __forceinline__ uint32_t pk(uint16_t a, uint16_t b) {
    return (uint32_t)a | ((uint32_t)b << 16);
}

__device__ __forceinline__ void mma16816(float acc[4], uint4 a, uint32_t b0, uint32_t b1) {
    asm volatile(
        "mma.sync.aligned.m16n8k16.row.col.f32.f16.f16.f32 "
        "{%0,%1,%2,%3},{%4,%5,%6,%7},{%8,%9},{%0,%1,%2,%3};"
        : "+f"(acc[0]), "+f"(acc[1]), "+f"(acc[2]), "+f"(acc[3])
        : "r"(a.x), "r"(a.y), "r"(a.z), "r"(a.w), "r"(b0), "r"(b1));
}

// ---- prep: pack codebook fragments (hi/lo interleaved) + exact ||c||^2 ----
__global__ void cbprep_kernel(const float* __restrict__ cb) {
    int t = blockIdx.x * blockDim.x + threadIdx.x;   // 0..16383
    int lane = t & 31, ks = (t >> 5) & 3, nt = t >> 7;
    int g = lane >> 2, tg = lane & 3;
    int n = nt * 8 + g;
    int k0 = ks * 16 + 2 * tg;
    const float* row = cb + (size_t)n * DD;
    float v0 = row[k0], v1 = row[k0 + 1], v2 = row[k0 + 8], v3 = row[k0 + 9];
    uint16_t h0, l0, h1, l1, h2, l2, h3, l3;
    split16(v0, h0, l0); split16(v1, h1, l1);
    split16(v2, h2, l2); split16(v3, h3, l3);
    g_b[t] = make_uint4(pk(h0, h1), pk(h2, h3), pk(l0, l1), pk(l2, l3));

    if (t < KK) {
        const float4* r4 = (const float4*)(cb + (size_t)t * DD);
        float s0 = 0.f, s1 = 0.f, s2 = 0.f, s3 = 0.f;
        #pragma unroll
        for (int q = 0; q < DD / 4; q++) {
            float4 c = r4[q];
            s0 = fmaf(c.x, c.x, s0);
            s1 = fmaf(c.y, c.y, s1);
            s2 = fmaf(c.z, c.z, s2);
            s3 = fmaf(c.w, c.w, s3);
        }
        float norm = (s0 + s1) + (s2 + s3);
        g_norm[t] = norm;
        g_mh[t]   = -0.5f * norm;
    }
}

// ---- shared layout ----
// Main phase: sah/sal (A fragments), smh. Output phase: those regions are dead
// and get reused as srow[128][68] floats (34816 B < OFF_SIDX).
#define OFF_AH   0            // 1024 x uint4  16 KB; reused: rescue scratch + srow
#define OFF_AL   16384        // 16 KB
#define OFF_MH   32768        // float[1024]    4 KB
#define OFF_SIDX 36864        // int[128]
#define OFF_FLG  37376        // int[128]
#define OFF_NFLG 37888        // int
#define SMEM_TOTAL 38016
#define ROWSTRIDE 68          // floats; 272B = 17*16 (float4-aligned, conflict-free)

// Branch-free top-2 update.
// Strict > keeps the FIRST (lowest-k) max; duplicate max -> sec==best -> flagged.
#define UPD(s, kk, ii)                                   \
    {                                                    \
        float _mn = fminf((s), best[ii]);                \
        bidx[ii] = ((s) > best[ii]) ? (kk) : bidx[ii];   \
        best[ii] = fmaxf((s), best[ii]);                 \
        sec[ii]  = fmaxf(sec[ii], _mn);                  \
    }

__global__ void __launch_bounds__(NTHR, 2) vq_kernel(
    const float* __restrict__ x,
    const float* __restrict__ cb,
    float* __restrict__ out,
    int write_idx
) {
    extern __shared__ char smem[];
    uint4* sah = (uint4*)(smem + OFF_AH);
    uint4* sal = (uint4*)(smem + OFF_AL);
    float* smh = (float*)(smem + OFF_MH);
    int*   sidx = (int*)(smem + OFF_SIDX);
    int*   sflg = (int*)(smem + OFF_FLG);
    int*   nflg = (int*)(smem + OFF_NFLG);

    const int tid = threadIdx.x;
    const int w = tid >> 5, lane = tid & 31;
    const int g = lane >> 2, tg = lane & 3;

    const int p0 = blockIdx.x * MT;
    const int b  = p0 >> 12;
    const int n0 = p0 & (HWN - 1);
    const float* xb = x + (size_t)b * DD * HWN + n0;

    if (tid == 0) *nflg = 0;
    for (int i = tid; i < KK; i += NTHR) smh[i] = g_mh[i];

    // ---- stage A: x[b, k, n0+m] -> fp16 hi/lo fragment layout (one-time) ----
    #pragma unroll
    for (int i = 0; i < 4; i++) {
        int f  = tid + i * NTHR;
        int fl = f & 31, ks = (f >> 5) & 3, mt = f >> 7;   // mt = 0..7 (one per warp)
        int fg = fl >> 2, ftg = fl & 3;
        int m  = mt * 16 + fg;
        int k0 = ks * 16 + 2 * ftg;
        const float* p = xb + m;
        const float* q = p + 8;
        float v00 = p[(size_t)k0 * HWN],       v01 = p[(size_t)(k0 + 1) * HWN];
        float v02 = p[(size_t)(k0 + 8) * HWN], v03 = p[(size_t)(k0 + 9) * HWN];
        float v10 = q[(size_t)k0 * HWN],       v11 = q[(size_t)(k0 + 1) * HWN];
        float v12 = q[(size_t)(k0 + 8) * HWN], v13 = q[(size_t)(k0 + 9) * HWN];
        uint16_t h[8], l[8];
        split16(v00, h[0], l[0]); split16(v01, h[1], l[1]);
        split16(v02, h[2], l[2]); split16(v03, h[3], l[3]);
        split16(v10, h[4], l[4]); split16(v11, h[5], l[5]);
        split16(v12, h[6], l[6]); split16(v13, h[7], l[7]);
        uint4 H = make_uint4(pk(h[0], h[1]), pk(h[4], h[5]), pk(h[2], h[3]), pk(h[6], h[7]));
        uint4 L = make_uint4(pk(l[0], l[1]), pk(l[4], l[5]), pk(l[2], l[3]), pk(l[6], l[7]));
        int idx = (mt * 4 + ks) * 32 + fl;
        sah[idx] = H;
        sal[idx] = L;
    }
    __syncthreads();

    // ---- A fragments -> registers, once for the whole kernel ----
    uint4 AH[4], AL[4];
    #pragma unroll
    for (int ks = 0; ks < 4; ks++) {
        AH[ks] = sah[(w * 4 + ks) * 32 + lane];
        AL[ks] = sal[(w * 4 + ks) * 32 + lane];
    }

    float best[2], sec[2];
    int   bidx[2];
    #pragma unroll
    for (int i = 0; i < 2; i++) { best[i] = -3.4e38f; sec[i] = -3.4e38f; bidx[i] = 0; }

    // ---- double-buffered B pipeline: batch = (ks, j-group of 4) -> 4 LDG + 12 MMA
    uint4 bvA[4], bvB[4];
    #pragma unroll
    for (int jj = 0; jj < 4; jj++)          // prime: ch=0, bt=0 (ks=0, j=0..3)
        bvA[jj] = __ldg(g_b + lane + (jj * 4) * 32);

    for (int ch = 0; ch < NCHUNK; ch++) {
        // acc init = -0.5||c||^2 (mh folded in; MMA accumulates dot on top)
        float acc[8][4];
        #pragma unroll
        for (int j = 0; j < 8; j++) {
            float2 mhv = *(const float2*)&smh[ch * NC + j * 8 + 2 * tg];
            acc[j][0] = mhv.x; acc[j][1] = mhv.y;
            acc[j][2] = mhv.x; acc[j][3] = mhv.y;
        }

        #pragma unroll
        for (int bt = 0; bt < 8; bt++) {
            uint4* cur = (bt & 1) ? bvB : bvA;
            uint4* nxt = (bt & 1) ? bvA : bvB;
            int nb  = bt + 1;
            int nch = (ch + (nb >> 3)) & (NCHUNK - 1);
            nb &= 7;
            int nks = nb >> 1, njg = (nb & 1) * 4;
            const uint4* np = g_b + (size_t)nch * 1024 + lane;
            #pragma unroll
            for (int jj = 0; jj < 4; jj++)
                nxt[jj] = __ldg(np + ((njg + jj) * 4 + nks) * 32);

            int ks = bt >> 1, jg = (bt & 1) * 4;
            #pragma unroll
            for (int jj = 0; jj < 4; jj++) mma16816(acc[jg + jj], AH[ks], cur[jj].x, cur[jj].y);
            #pragma unroll
            for (int jj = 0; jj < 4; jj++) mma16816(acc[jg + jj], AH[ks], cur[jj].z, cur[jj].w);
            #pragma unroll
            for (int jj = 0; jj < 4; jj++) mma16816(acc[jg + jj], AL[ks], cur[jj].x, cur[jj].y);
        }

        // branch-free top-2 epilogue (ascending k); scores already include mh
        #pragma unroll
        for (int j = 0; j < 8; j++) {
            int kb = ch * NC + j * 8 + 2 * tg;
            UPD(acc[j][0], kb,     0);
            UPD(acc[j][1], kb + 1, 0);
            UPD(acc[j][2], kb,     1);
            UPD(acc[j][3], kb + 1, 1);
        }
    }

    // cross-lane top-2 merge (4 lanes per point), index tie-break
    #pragma unroll
    for (int i = 0; i < 2; i++) {
        #pragma unroll
        for (int m = 1; m <= 2; m <<= 1) {
            float ob = __shfl_xor_sync(0xffffffffu, best[i], m);
            float os = __shfl_xor_sync(0xffffffffu, sec[i], m);
            int   oi = __shfl_xor_sync(0xffffffffu, bidx[i], m);
            if (ob > best[i] || (ob == best[i] && oi < bidx[i])) {
                float t = best[i];
                best[i] = ob; bidx[i] = oi;
                sec[i] = (os > t) ? os : t;
            } else {
                sec[i] = (ob > sec[i]) ? ob : sec[i];
            }
        }
    }
    if (tg == 0) {
        #pragma unroll
        for (int i = 0; i < 2; i++) {
            int pl = w * 16 + i * 8 + g;
            sidx[pl] = bidx[i];
            if (best[i] - sec[i] < MARGIN) {
                int slot = atomicAdd(nflg, 1);
                if (slot < MT) sflg[slot] = pl;
            }
        }
    }
    __syncthreads();

    // ---- exact fp32 rescue (verified: bit-matches the reference) ----
    {
        int nfr = *nflg;
        int overflow = (nfr > MT);
        int nf = overflow ? MT : nfr;
        float* xs = (float*)(smem + OFF_AH) + w * 64;   // sah dead now
        for (int f = w; f < nf; f += 8) {
            int pl = overflow ? f : sflg[f];
            xs[lane]      = xb[(size_t)lane * HWN + pl];
            xs[lane + 32] = xb[(size_t)(lane + 32) * HWN + pl];
            __syncwarp();
            float bb = 3.4e38f;
            int   bi = 0;
            for (int j = 0; j < 32; j++) {
                int k = j * 32 + lane;
                const float4* crow = (const float4*)(cb + (size_t)k * DD);
                float d0 = 0.f, d1 = 0.f, d2 = 0.f, d3 = 0.f;
                #pragma unroll
                for (int q = 0; q < 16; q++) {
                    float4 c = __ldg(crow + q);
                    d0 = fmaf(xs[4 * q + 0], c.x, d0);
                    d1 = fmaf(xs[4 * q + 1], c.y, d1);
                    d2 = fmaf(xs[4 * q + 2], c.z, d2);
                    d3 = fmaf(xs[4 * q + 3], c.w, d3);
                }
                float dot = (d0 + d1) + (d2 + d3);
                float s   = fmaf(-2.0f, dot, __ldg(&g_norm[k]));
                if (s < bb) { bb = s; bi = k; }
            }
            #pragma unroll
            for (int m = 16; m >= 1; m >>= 1) {
                float ob = __shfl_xor_sync(0xffffffffu, bb, m);
                int   oi = __shfl_xor_sync(0xffffffffu, bi, m);
                if (ob < bb || (ob == bb && oi < bi)) { bb = ob; bi = oi; }
            }
            if (lane == 0) sidx[pl] = bi;
            __syncwarp();
        }
    }
    __syncthreads();

    // ---- output gather via smem row-bounce (row-coalesced loads) ----
    float* srow = (float*)(smem + OFF_AH);   // [128][ROWSTRIDE] floats, 34816 B
    {
        // Phase 1: each warp copies its 16 selected rows, 2 rows per iteration.
        // lanes 0-15 -> row of point pl, lanes 16-31 -> row of point pl+1.
        #pragma unroll
        for (int i = 0; i < 8; i++) {
            int pl  = w * 16 + i * 2 + (lane >> 4);
            int ll  = lane & 15;
            int row = sidx[pl];
            float4 v = __ldg((const float4*)(cb + (size_t)row * DD) + ll);
            *((float4*)(srow + pl * ROWSTRIDE) + ll) = v;
        }
    }
    __syncthreads();
    {
        // Phase 2: coalesced drain. Thread reads float4 (4 d's of one point),
        // writes 4 same-d consecutive-pl stores (fully coalesced).
        float* ob = out + (size_t)b * DD * HWN + n0;
        #pragma unroll
        for (int it = 0; it < 8; it++) {
            int f    = tid + it * NTHR;
            int pl   = f & (MT - 1);
            int dblk = f >> 7;           // 0..15
            float4 v = *((const float4*)(srow + pl * ROWSTRIDE) + dblk);
            ob[(size_t)(dblk * 4 + 0) * HWN + pl] = v.x;
            ob[(size_t)(dblk * 4 + 1) * HWN + pl] = v.y;
            ob[(size_t)(dblk * 4 + 2) * HWN + pl] = v.z;
            ob[(size_t)(dblk * 4 + 3) * HWN + pl] = v.w;
        }
    }
    if (write_idx && tid < MT)
        out[(size_t)BB * DD * HWN + p0 + tid] = (float)sidx[tid];
}

extern "C" void kernel_launch(void* const* d_in, const int* in_sizes, int n_in,
                              void* d_out, int out_size) {
    const float* x  = (const float*)d_in[0];
    const float* cb = (const float*)d_in[1];
    float* out = (float*)d_out;

    static int inited = 0;
    if (!inited) {
        cudaFuncSetAttribute(vq_kernel, cudaFuncAttributeMaxDynamicSharedMemorySize, SMEM_TOTAL);
        inited = 1;
    }

    cbprep_kernel<<<64, 256>>>(cb);

    int write_idx = (out_size >= BB * DD * HWN + NPTS) ? 1 : 0;
    vq_kernel<<<NPTS / MT, NTHR, SMEM_TOTAL>>>(x, cb, out, write_idx);
}